// round 15
// baseline (speedup 1.0000x reference)
#include <cuda_runtime.h>

// grid [2,160,160,160,3] float32
#define BB 2
#define NX 160
#define NY 160
#define NZ 160

#define TY 13                     // 12 y-tiles of 13 rows
#define NCHUNK 6                  // z chunks, 28 outputs each (168 >= 156)
#define XSPLIT 3
#define XSTEPS 52                 // 156 / XSPLIT
#define NTHREADS (TY*32)          // 416
#define NBLOCKS (NCHUNK*12*BB*XSPLIT) // 432 = 2.92/SM @ occ3: ONE round, halved fixed costs

#define RY (TY + 4)               // 17
#define RZ_ST 32                  // staged z per slice (z0-2 .. z0+29)
#define SLICE (RY * RZ_ST * 3)    // 1632 floats = 6528 B
#define ROWW (NZ * 3)             // 480 floats per (b,x,y) row
#define CPR (RZ_ST * 3 / 4)       // 24 16B chunks per staged row
#define CHUNKS (RY * CPR)         // 408 <= 416: one predicated cp16 per thread

__device__ double g_be_sum;
__device__ unsigned int g_be_cnt;

__device__ __forceinline__ void cp16(unsigned int dst_smem, const float* src) {
    asm volatile("cp.async.cg.shared.global [%0], [%1], 16;" :: "r"(dst_smem), "l"(src));
}
__device__ __forceinline__ void cp_commit() {
    asm volatile("cp.async.commit_group;" ::: "memory");
}
__device__ __forceinline__ void cp_wait0() {
    asm volatile("cp.async.wait_group 0;" ::: "memory");
}
__device__ __forceinline__ void cp_wait1() {
    asm volatile("cp.async.wait_group 1;" ::: "memory");
}

#define SHUP(v)  __shfl_up_sync(0xffffffffu, (v), 1)
#define SHDN(v)  __shfl_down_sync(0xffffffffu, (v), 1)
#define SHUP2(v) __shfl_up_sync(0xffffffffu, (v), 2)
#define SHDN2(v) __shfl_down_sync(0xffffffffu, (v), 2)

__global__ __launch_bounds__(NTHREADS, 3)
void be_main_kernel(const float* __restrict__ g, float* __restrict__ out) {
    __shared__ float ring[5 * SLICE];       // 32.6 KB static
    __shared__ float warp_part[TY];

    const int tz  = threadIdx.x;            // 0..31 (lane)
    const int ty  = threadIdx.y;            // 0..12
    const int tid = ty * 32 + tz;

    const int cz  = blockIdx.x;             // 0..5   z chunk (28 outputs each)
    const int cy  = blockIdx.y;             // 0..11  y tile (13 rows)
    const int b   = blockIdx.z / XSPLIT;
    const int seg = blockIdx.z % XSPLIT;

    const int z0 = 2 + cz * 28;             // first output z of this chunk
    const int y0 = 2 + cy * TY;
    const int xs = 2 + seg * XSTEPS;

    // lane l holds center z = z0 - 2 + l; outputs come from lanes 2..29
    const int zc = z0 - 2 + tz;
    const bool active = (tz >= 2) && (tz <= 29) && (zc <= NZ - 3);

    // ---- staging map: one predicated 16B chunk per thread (408 of 416) ----
    const int zbase3 = (z0 - 2) * 3;        // = 84*cz floats, 16B-aligned
    int goff;
    const bool stg = (tid < CHUNKS);
    {
        int t = stg ? tid : 0;
        int row = t / CPR, col = t - row * CPR;
        int o = zbase3 + col * 4;
        if (o > ROWW - 4) o = ROWW - 4;     // clamp: lands in unread lane-halo slack
        goff = row * ROWW + o;
    }

    const long long bbase = (long long)b * NX * NY * ROWW + (long long)(y0 - 2) * ROWW;
    const unsigned int ring_s = (unsigned int)__cvta_generic_to_shared(ring);

    auto issue_slice = [&](int gx, int slot) {
        const float* src = g + bbase + (long long)gx * (NY * ROWW);
        if (stg)
            cp16(ring_s + (unsigned int)(slot * SLICE) * 4u + (unsigned int)tid * 16u,
                 src + goff);
    };

    // ---- slot(x) = (x - xs + 2) mod 5; prologue: xs-2..xs+1 -> slots 0..3 ----
    issue_slice(xs - 2, 0);
    issue_slice(xs - 1, 1);
    issue_slice(xs,     2);
    issue_slice(xs + 1, 3);
    cp_commit();
    cp_wait0();
    __syncthreads();

    const int off0 = ((ty + 2) * RZ_ST + tz) * 3;
    #define Y (RZ_ST * 3)
    #define Zw 3

    // center delay lines: c0 x+2..x-2; c1,c2 x+2..x
    float c0a, c0b, c0c, c0d, c0e;
    float c1p2, c1p1, c1z, c2p2, c2p1, c2z;
    // q delay lines: q(s) = S_s[+off] - S_s[-off]
    float q2_xy0, q2_xy1, q2_xz0, q2_xz1, q2_xz2;
    float q1_xy0, q1_xy1, q1_xy2, q1_xz0, q1_xz1, q1_xz2;
    {
        const float* s;
        s = ring + 3 * SLICE; c0a = s[off0]; c1p2 = s[off0 + 1]; c2p2 = s[off0 + 2]; // xs+1
        s = ring + 2 * SLICE; c0b = s[off0]; c1p1 = s[off0 + 1]; c2p1 = s[off0 + 2]; // xs
        q1_xy0 = s[off0 + Y]      - s[off0 - Y];
        q1_xy1 = s[off0 + Y + 1]  - s[off0 - Y + 1];
        q1_xy2 = s[off0 + Y + 2]  - s[off0 - Y + 2];
        q1_xz0 = s[off0 + Zw]     - s[off0 - Zw];
        q1_xz1 = s[off0 + Zw + 1] - s[off0 - Zw + 1];
        q1_xz2 = s[off0 + Zw + 2] - s[off0 - Zw + 2];
        s = ring + 1 * SLICE; c0c = s[off0];                                          // xs-1
        q2_xy0 = s[off0 + Y]      - s[off0 - Y];
        q2_xy1 = s[off0 + Y + 1]  - s[off0 - Y + 1];
        q2_xz0 = s[off0 + Zw]     - s[off0 - Zw];
        q2_xz1 = s[off0 + Zw + 1] - s[off0 - Zw + 1];
        q2_xz2 = s[off0 + Zw + 2] - s[off0 - Zw + 2];
        s = ring;             c0d = s[off0];                                          // xs-2
        c0e = 0.f; c1z = 0.f; c2z = 0.f;
    }
    __syncthreads();            // init reads done before slot 0/4 reuse

    // pipeline: xs+2 -> slot 4, xs+3 -> slot 0 (two groups in flight)
    issue_slice(xs + 2, 4); cp_commit();
    issue_slice(xs + 3, 0); cp_commit();

    float acc = 0.0f;
    int gx4 = xs + 4;

    #define DO_STEP(SM1i, S0i, SP1i, SP2i)                                        \
    {                                                                             \
        cp_wait1();                                                               \
        __syncthreads();                                                          \
        {                                                                         \
            int gxs = gx4 > (NX - 1) ? (NX - 1) : gx4;                            \
            issue_slice(gxs, (SM1i)); cp_commit(); ++gx4;                         \
        }                                                                         \
        {                                                                         \
            const float* sp = ring + (SP2i) * SLICE;                              \
            float n0 = sp[off0], n1 = sp[off0 + 1], n2 = sp[off0 + 2];            \
            c0e = c0d; c0d = c0c; c0c = c0b; c0b = c0a; c0a = n0;                 \
            c1z = c1p1; c1p1 = c1p2; c1p2 = n1;                                   \
            c2z = c2p1; c2p1 = c2p2; c2p2 = n2;                                   \
        }                                                                         \
        const float* Sp1 = ring + (SP1i) * SLICE;                                 \
        const float qn_xy0 = Sp1[off0 + Y]     - Sp1[off0 - Y];                   \
        const float qn_xy1 = Sp1[off0 + Y + 1] - Sp1[off0 - Y + 1];               \
        const float qn_xy2 = Sp1[off0 + Y + 2] - Sp1[off0 - Y + 2];               \
        const float qn_xz0 = SHDN(c0b)  - SHUP(c0b);                              \
        const float qn_xz1 = SHDN(c1p1) - SHUP(c1p1);                             \
        const float qn_xz2 = SHDN(c2p1) - SHUP(c2p1);                             \
        const float dyz0 = SHDN(q1_xy0) - SHUP(q1_xy0);                           \
        const float dyz1 = SHDN(q1_xy1) - SHUP(q1_xy1);                           \
        const float dyz2 = SHDN(q1_xy2) - SHUP(q1_xy2);                           \
        const float dzz0 = SHUP2(c0c) + SHDN2(c0c) - 2.0f * c0c;                  \
        const float dzz1 = SHUP2(c1z) + SHDN2(c1z) - 2.0f * c1z;                  \
        const float dzz2 = SHUP2(c2z) + SHDN2(c2z) - 2.0f * c2z;                  \
        if (active) {                                                             \
            const float* S0 = ring + (S0i) * SLICE;                               \
            const float dxx0 = c0e + c0a - 2.0f * c0c;                            \
            const float dyy0 = S0[off0 - 2*Y]     + S0[off0 + 2*Y]     - 2.0f * c0c; \
            const float dyy1 = S0[off0 - 2*Y + 1] + S0[off0 + 2*Y + 1] - 2.0f * c1z; \
            const float dxy0 = qn_xy0 - q2_xy0;                                   \
            const float dxy1 = qn_xy1 - q2_xy1;                                   \
            const float dxz0 = qn_xz0 - q2_xz0;                                   \
            const float dxz1 = qn_xz1 - q2_xz1;                                   \
            const float dxz2 = qn_xz2 - q2_xz2;                                   \
            float s1 = dxx0 * dxx0;                                               \
            s1 = fmaf(dyy1, dyy1, s1);                                            \
            s1 = fmaf(dxy1, dxy1, s1);                                            \
            s1 = fmaf(dzz2, dzz2, s1);                                            \
            s1 = fmaf(dxz2, dxz2, s1);                                            \
            s1 = fmaf(dyz2, dyz2, s1);                                            \
            float s2 = dyy0 * dyy0;                                               \
            s2 = fmaf(dzz0, dzz0, s2);                                            \
            s2 = fmaf(dzz1, dzz1, s2);                                            \
            s2 = fmaf(dxz1, dxz1, s2);                                            \
            float s3 = dxy0 * dxy0;                                               \
            s3 = fmaf(dxz0, dxz0, s3);                                            \
            s3 = fmaf(dyz1, dyz1, s3);                                            \
            float t = fmaf(2.0f, s2, s1);                                         \
            t = fmaf(3.0f, s3, t);                                                \
            t = fmaf(4.0f * dyz0, dyz0, t);                                       \
            acc += t;                                                             \
        }                                                                         \
        q2_xy0 = q1_xy0; q2_xy1 = q1_xy1;                                         \
        q2_xz0 = q1_xz0; q2_xz1 = q1_xz1; q2_xz2 = q1_xz2;                        \
        q1_xy0 = qn_xy0; q1_xy1 = qn_xy1; q1_xy2 = qn_xy2;                        \
        q1_xz0 = qn_xz0; q1_xz1 = qn_xz1; q1_xz2 = qn_xz2;                        \
    }

    // 52 steps = 10 x 5 + 2; slot pattern period 5 (all literals)
    #pragma unroll 1
    for (int it = 0; it < 10; ++it) {
        DO_STEP(1, 2, 3, 4);
        DO_STEP(2, 3, 4, 0);
        DO_STEP(3, 4, 0, 1);
        DO_STEP(4, 0, 1, 2);
        DO_STEP(0, 1, 2, 3);
    }
    DO_STEP(1, 2, 3, 4);        // step 50
    DO_STEP(2, 3, 4, 0);        // step 51

    #undef DO_STEP
    #undef Y
    #undef Zw

    // block reduction
    float v = acc;
    #pragma unroll
    for (int o = 16; o > 0; o >>= 1) v += __shfl_down_sync(0xffffffffu, v, o);
    if (tz == 0) warp_part[ty] = v;
    __syncthreads();
    if (tid == 0) {
        float s = 0.0f;
        #pragma unroll
        for (int w = 0; w < TY; ++w) s += warp_part[w];
        atomicAdd(&g_be_sum, (double)s);
        __threadfence();
        unsigned int t = atomicAdd(&g_be_cnt, 1u);
        if (t == NBLOCKS - 1) {
            double total = atomicAdd(&g_be_sum, 0.0);   // ordered read of final sum
            const double n = (double)BB * 156.0 * 156.0 * 156.0 * 3.0;
            out[0] = (float)(total / (16.0 * n));
            g_be_cnt = 0;        // reset for next (graph-replayed) launch
            g_be_sum = 0.0;
        }
    }
}

extern "C" void kernel_launch(void* const* d_in, const int* in_sizes, int n_in,
                              void* d_out, int out_size) {
    const float* grid = (const float*)d_in[0];
    float* out = (float*)d_out;

    dim3 blk(32, TY, 1);
    dim3 grd(NCHUNK, 12, BB * XSPLIT);
    be_main_kernel<<<grd, blk>>>(grid, out);
}